// round 12
// baseline (speedup 1.0000x reference)
#include <cuda_runtime.h>
#include <cuda_bf16.h>
#include <cstdint>

// AFM forward, algebraically collapsed (softmax over size-1 axis == 1):
//   x[b]   = 0.5*(||sum_f emb_f||^2 - sum_f ||emb_f||^2)
//   out[b] = sigmoid(x[b]*out_kernel + out_bias)
//
// Shape: ONE WARP PER ROW, 1024 CTAs x 128 threads (best measured).
// Change vs R11: gathers go through cp.async.cg (LDGSTS, L1-bypass) into
// per-lane smem slots instead of LDG. Eleven rounds show the limiter is
// the per-SM outstanding-LDG-miss cap (~61 in flight/SM == measured
// 107k req / 7.1us / 533ns). LDGSTS has no observed depth cap on B300 --
// a different outstanding pool. Same request count (64B per embedding).

#define B_ROWS   4096
#define N_SPARSE 26
#define VOCAB    100000

__global__ void __launch_bounds__(128) afm_gather_kernel(
    const int*    __restrict__ ids,     // [B, 26]
    const float4* __restrict__ table,   // [26, VOCAB, 4] float4 units
    const float*  __restrict__ out_k,   // [1]
    const float*  __restrict__ out_b,   // [1]
    float*        __restrict__ out)     // [B]
{
    const unsigned FULL = 0xffffffffu;

    // [warp][round][lane] 16B slots: 4*4*32*16B = 8KB. Lane writes and
    // reads ONLY its own slot -> wait_group 0 gives sufficient ordering.
    __shared__ __align__(16) float4 buf[4][4][32];

    const int gtid = blockIdx.x * blockDim.x + threadIdx.x;
    const int row  = gtid >> 5;            // one warp per row (grid exact)
    const int w    = threadIdx.x >> 5;     // warp in block 0..3
    const int lane = threadIdx.x & 31;

    const int slice = lane & 3;            // float4 slice of the embedding
    const int fg    = lane >> 2;           // field-in-group 0..7

    const int* rid = ids + row * N_SPARSE;

    const float okv = __ldg(out_k);
    const float obv = __ldg(out_b);

    // Front-batched id loads: unconditional, clamped in-row (4-lane bcast).
    int idr[4];
    #pragma unroll
    for (int r = 0; r < 4; ++r) {
        int f = r * 8 + fg;
        idr[r] = __ldg(rid + (f < N_SPARSE ? f : N_SPARSE - 1));
    }

    // Issue all gathers as cp.async.cg (L1-bypass, deep outstanding pool).
    // 4 adjacent lanes' 16B copies of one embedding coalesce to one 64B
    // L2/DRAM transaction, same as the LDG version.
    #pragma unroll
    for (int r = 0; r < 4; ++r) {
        const int f = r * 8 + fg;
        if (f < N_SPARSE) {
            const float4* gp = table + (size_t)f * (VOCAB * 4)
                                     + (size_t)idr[r] * 4 + slice;
            const uint32_t sa = (uint32_t)__cvta_generic_to_shared(&buf[w][r][lane]);
            asm volatile("cp.async.cg.shared.global [%0], [%1], 16;"
                         :: "r"(sa), "l"(gp) : "memory");
        }
    }
    asm volatile("cp.async.commit_group;" ::: "memory");
    asm volatile("cp.async.wait_group 0;" ::: "memory");

    float4 S = make_float4(0.f, 0.f, 0.f, 0.f);
    float  q = 0.f;

    #pragma unroll
    for (int r = 0; r < 4; ++r) {
        const int f = r * 8 + fg;
        if (f < N_SPARSE) {
            const float4 v = buf[w][r][lane];   // own slot, conflict-free LDS.128
            S.x += v.x; S.y += v.y; S.z += v.z; S.w += v.w;
            q   += v.x * v.x + v.y * v.y + v.z * v.z + v.w * v.w;
        }
    }

    // Reduce S and q over the field dimension (lane bits 2,3,4).
    #pragma unroll
    for (int d = 4; d <= 16; d <<= 1) {
        S.x += __shfl_xor_sync(FULL, S.x, d);
        S.y += __shfl_xor_sync(FULL, S.y, d);
        S.z += __shfl_xor_sync(FULL, S.z, d);
        S.w += __shfl_xor_sync(FULL, S.w, d);
        q   += __shfl_xor_sync(FULL, q, d);
    }

    // Lanes 0..3 hold per-slice totals; merged tail reduction.
    float t = S.x * S.x + S.y * S.y + S.z * S.z + S.w * S.w - q;
    t += __shfl_xor_sync(FULL, t, 1);
    t += __shfl_xor_sync(FULL, t, 2);

    if (lane == 0) {
        const float z = 0.5f * t * okv + obv;   // t == 2*sum_{i<j} e_i.e_j
        out[row] = 1.0f / (1.0f + __expf(-z));
    }
}

extern "C" void kernel_launch(void* const* d_in, const int* in_sizes, int n_in,
                              void* d_out, int out_size)
{
    (void)in_sizes; (void)n_in; (void)out_size;
    const int*    ids   = (const int*)   d_in[1];
    const float4* table = (const float4*)d_in[2];
    const float*  out_k = (const float*) d_in[7];
    const float*  out_b = (const float*) d_in[8];
    float*        out   = (float*)       d_out;

    const int threads = 128;                     // 4 warps = 4 rows / block
    const int blocks  = (B_ROWS * 32) / threads; // 1024 blocks, exact
    afm_gather_kernel<<<blocks, threads>>>(ids, table, out_k, out_b, out);
}

// round 13
// speedup vs baseline: 1.0386x; 1.0386x over previous
#include <cuda_runtime.h>
#include <cuda_bf16.h>
#include <cstdint>

// AFM forward, algebraically collapsed (softmax over size-1 axis == 1):
//   x[b]   = 0.5*(||sum_f emb_f||^2 - sum_f ||emb_f||^2)
//   out[b] = sigmoid(x[b]*out_kernel + out_bias)
//
// Shape: ONE WARP PER ROW, 1024 CTAs x 128 threads.
// Change vs R10/R12: DUAL-ENGINE gather. The limiter is the per-SM
// outstanding-miss pool on the LSU/L1tex path (LDG and cp.async.cg both
// pin at ~6.6-6.9us). Fields 0..12 go via LDG (L2::64B hint); fields
// 13..25 go via cp.async.bulk (UBLKCP, TMA engine, mbarrier-completed)
// into smem. If the TMA engine's outstanding pool is independent, the
// two halves fetch in parallel.

#define B_ROWS   4096
#define N_SPARSE 26
#define VOCAB    100000

__device__ __forceinline__ float4 ldg_64b_v4(const float4* p) {
    float4 v;
    asm("ld.global.nc.L2::64B.v4.f32 {%0,%1,%2,%3}, [%4];"
        : "=f"(v.x), "=f"(v.y), "=f"(v.z), "=f"(v.w)
        : "l"(p));
    return v;
}

__global__ void __launch_bounds__(128) afm_gather_kernel(
    const int*    __restrict__ ids,     // [B, 26]
    const float4* __restrict__ table,   // [26, VOCAB, 4] float4 units
    const float*  __restrict__ out_k,   // [1]
    const float*  __restrict__ out_b,   // [1]
    float*        __restrict__ out)     // [B]
{
    const unsigned FULL = 0xffffffffu;

    // TMA destination: [warp][field 13..25] -> 64B embedding each. 3328B.
    __shared__ __align__(64) float4 buf[4][13][4];
    __shared__ __align__(8)  uint64_t mbar;

    const int gtid = blockIdx.x * blockDim.x + threadIdx.x;
    const int row  = gtid >> 5;            // one warp per row (grid exact)
    const int w    = threadIdx.x >> 5;     // warp in block 0..3
    const int lane = threadIdx.x & 31;

    const int slice = lane & 3;
    const int fg    = lane >> 2;           // 0..7

    const int* rid = ids + row * N_SPARSE;

    const float okv = __ldg(out_k);
    const float obv = __ldg(out_b);

    const uint32_t mb = (uint32_t)__cvta_generic_to_shared(&mbar);

    // Init barrier; expect 4 rows x 13 fields x 64B. Single arrive.
    if (threadIdx.x == 0) {
        asm volatile("mbarrier.init.shared.b64 [%0], 1;" :: "r"(mb) : "memory");
        asm volatile("mbarrier.arrive.expect_tx.shared.b64 _, [%0], %1;"
                     :: "r"(mb), "r"(4 * 13 * 64) : "memory");
    }
    __syncthreads();

    // TMA half: lanes 0..12 each bulk-copy one 64B embedding (fields 13..25).
    if (lane < 13) {
        const int f  = 13 + lane;
        const int id = __ldg(rid + f);
        const float4* gp = table + (size_t)f * (VOCAB * 4) + (size_t)id * 4;
        const uint32_t sa = (uint32_t)__cvta_generic_to_shared(&buf[w][lane][0]);
        asm volatile(
            "cp.async.bulk.shared::cta.global.mbarrier::complete_tx::bytes "
            "[%0], [%1], 64, [%2];"
            :: "r"(sa), "l"(gp), "r"(mb) : "memory");
    }

    // LDG half (overlapped with TMA): fields 0..12, 2 rounds.
    int idr[2];
    #pragma unroll
    for (int r = 0; r < 2; ++r) {
        int fl = r * 8 + fg;
        idr[r] = __ldg(rid + (fl < 13 ? fl : 12));
    }

    float4 S = make_float4(0.f, 0.f, 0.f, 0.f);
    float  q = 0.f;

    #pragma unroll
    for (int r = 0; r < 2; ++r) {
        const int fl = r * 8 + fg;
        if (fl < 13) {
            const float4 v = ldg_64b_v4(table + (size_t)fl * (VOCAB * 4)
                                              + (size_t)idr[r] * 4 + slice);
            S.x += v.x; S.y += v.y; S.z += v.z; S.w += v.w;
            q   += v.x * v.x + v.y * v.y + v.z * v.z + v.w * v.w;
        }
    }

    // Wait for the TMA half (phase 0 every launch; fresh barrier per launch).
    {
        uint32_t done;
        asm volatile(
            "{\n\t.reg .pred p;\n\t"
            "mbarrier.try_wait.parity.acquire.cta.shared::cta.b64 p, [%1], 0;\n\t"
            "selp.b32 %0, 1, 0, p;\n\t}"
            : "=r"(done) : "r"(mb) : "memory");
        while (!done) {
            asm volatile(
                "{\n\t.reg .pred p;\n\t"
                "mbarrier.try_wait.parity.acquire.cta.shared::cta.b64 p, [%1], 0, 0x989680;\n\t"
                "selp.b32 %0, 1, 0, p;\n\t}"
                : "=r"(done) : "r"(mb) : "memory");
        }
    }

    // Accumulate the TMA half from smem (conflict-free: 512B contiguous/warp).
    #pragma unroll
    for (int r = 0; r < 2; ++r) {
        const int fl = r * 8 + fg;
        if (fl < 13) {
            const float4 v = buf[w][fl][slice];
            S.x += v.x; S.y += v.y; S.z += v.z; S.w += v.w;
            q   += v.x * v.x + v.y * v.y + v.z * v.z + v.w * v.w;
        }
    }

    // Reduce S and q over the field dimension (lane bits 2,3,4).
    #pragma unroll
    for (int d = 4; d <= 16; d <<= 1) {
        S.x += __shfl_xor_sync(FULL, S.x, d);
        S.y += __shfl_xor_sync(FULL, S.y, d);
        S.z += __shfl_xor_sync(FULL, S.z, d);
        S.w += __shfl_xor_sync(FULL, S.w, d);
        q   += __shfl_xor_sync(FULL, q, d);
    }

    // Lanes 0..3 hold per-slice totals; merged tail reduction.
    float t = S.x * S.x + S.y * S.y + S.z * S.z + S.w * S.w - q;
    t += __shfl_xor_sync(FULL, t, 1);
    t += __shfl_xor_sync(FULL, t, 2);

    if (lane == 0) {
        const float z = 0.5f * t * okv + obv;   // t == 2*sum_{i<j} e_i.e_j
        out[row] = 1.0f / (1.0f + __expf(-z));
    }
}

extern "C" void kernel_launch(void* const* d_in, const int* in_sizes, int n_in,
                              void* d_out, int out_size)
{
    (void)in_sizes; (void)n_in; (void)out_size;
    const int*    ids   = (const int*)   d_in[1];
    const float4* table = (const float4*)d_in[2];
    const float*  out_k = (const float*) d_in[7];
    const float*  out_b = (const float*) d_in[8];
    float*        out   = (float*)       d_out;

    const int threads = 128;                     // 4 warps = 4 rows / block
    const int blocks  = (B_ROWS * 32) / threads; // 1024 blocks, exact
    afm_gather_kernel<<<blocks, threads>>>(ids, table, out_k, out_b, out);
}